// round 11
// baseline (speedup 1.0000x reference)
#include <cuda_runtime.h>
#include <cuda_fp16.h>
#include <cstdint>

#define NN 100000
#define EE 800000
#define TT 3
#define D  128
#define TND (TT * NN)
#define NCTA 782           // ceil(NN/128)
#define TILE_BYTES 34816   // 128 * 272
#define BKT 48             // CSR bucket entries per (type,node); P(deg>48) ~ 3e-15
#define ZOFF (TND << 8)    // byte offset of the shared zero row

// ---------------- device scratch (no allocs allowed) ----------------
__device__ __half g_xws[((size_t)TND + 1) * D];     // 76.8 MB fp16 dis-scaled xw + zero row
__device__ uint4  g_wb[TT * (TILE_BYTES / 16)];     // W fp16 pre-baked smem images
__device__ int    g_cur[TND];                       // bucket fill cursor (starts at 1: self)
__device__ float  g_dis[TND];
__device__ int4   g_meta[TND];                      // {csr_base, cnt, dis_bits, cnt_pad4}
__device__ int    g_csr[(size_t)TND * BKT];         // absolute byte offsets ((t*NN+src)*256)

// ---------------- helpers ----------------
__device__ __forceinline__ uint32_t smem_u32(const void* p) {
    uint32_t a;
    asm("{ .reg .u64 t; cvta.to.shared.u64 t, %1; cvt.u32.u64 %0, t; }" : "=r"(a) : "l"(p));
    return a;
}

#define LDSM4(r0, r1, r2, r3, addr)                                              \
    asm volatile("ldmatrix.sync.aligned.m8n8.x4.shared.b16 {%0,%1,%2,%3}, [%4];" \
                 : "=r"(r0), "=r"(r1), "=r"(r2), "=r"(r3) : "r"(addr))

#define MMA_F16(d, a0, a1, a2, a3, b0, b1)                                    \
    asm volatile("mma.sync.aligned.m16n8k16.row.col.f32.f16.f16.f32 "         \
                 "{%0,%1,%2,%3}, {%4,%5,%6,%7}, {%8,%9}, {%0,%1,%2,%3};"      \
                 : "+f"(d[0]), "+f"(d[1]), "+f"(d[2]), "+f"(d[3])             \
                 : "r"(a0), "r"(a1), "r"(a2), "r"(a3), "r"(b0), "r"(b1))

// ---------------- init: cur=1, self entry, zero row, W fp16 prebake ----------------
__global__ void k_init(const float* __restrict__ W) {
    int i = blockIdx.x * blockDim.x + threadIdx.x;
    if (i < TND) {
        g_cur[i] = 1;                                // slot 0 = self loop
        g_csr[(size_t)i * BKT] = i << 8;             // self entry, absolute byte offset
    }
    if (i < 32)                                      // zero row (256B)
        ((uint2*)(g_xws + (size_t)TND * D))[i] = make_uint2(0u, 0u);
    if (i < TT * 128 * 32) {                         // W: one float4 per thread
        int t = i / (128 * 32);
        int k = (i >> 5) & 127;
        int c4 = i & 31;
        float4 v = *(const float4*)&W[(size_t)t * D * D + k * D + c4 * 4];
        float vv[4] = {v.x, v.y, v.z, v.w};
        unsigned char* img = (unsigned char*)g_wb + (size_t)t * TILE_BYTES;
#pragma unroll
        for (int j = 0; j < 4; j++) {
            int n = c4 * 4 + j;                      // output col -> B row
            *(__half*)(img + (size_t)n * 272 + k * 2) = __float2half_rn(vv[j]);
        }
    }
}

// ---------------- bucket fill: 4 edges per thread (EE % 4 == 0) ----------------
__global__ void k_fill(const int* __restrict__ edges) {
    int i = blockIdx.x * blockDim.x + threadIdx.x;
    if (i >= TT * (EE / 4)) return;
    int t = i / (EE / 4), e4 = i - t * (EE / 4);
    const int* et = edges + (size_t)t * 2 * EE;
    int4 s = __ldg((const int4*)et + e4);
    int4 d = __ldg((const int4*)(et + EE) + e4);
    int* cur = g_cur + t * NN;
    int tb = t * NN;
    int p;
    p = atomicAdd(&cur[d.x], 1); if (p < BKT) g_csr[(size_t)(tb + d.x) * BKT + p] = (tb + s.x) << 8;
    p = atomicAdd(&cur[d.y], 1); if (p < BKT) g_csr[(size_t)(tb + d.y) * BKT + p] = (tb + s.y) << 8;
    p = atomicAdd(&cur[d.z], 1); if (p < BKT) g_csr[(size_t)(tb + d.z) * BKT + p] = (tb + s.z) << 8;
    p = atomicAdd(&cur[d.w], 1); if (p < BKT) g_csr[(size_t)(tb + d.w) * BKT + p] = (tb + s.w) << 8;
}

// ---------------- meta: cnt + dis from cursors; pad buckets to mult of 4 ----------------
__global__ void k_meta() {
    int i = blockIdx.x * blockDim.x + threadIdx.x;
    if (i >= TND) return;
    int c = g_cur[i];
    c = (c < BKT) ? c : BKT;
    int c4 = (c + 3) & ~3;                           // padded count
    for (int s = c; s < c4; s++)                     // pad with zero-row entries
        g_csr[(size_t)i * BKT + s] = ZOFF;
    float dn = rsqrtf((float)c);                     // deg incl. self == entry count
    g_dis[i] = dn;
    g_meta[i] = make_int4(i * BKT, c, __float_as_int(dn), c4);
}

// ---------------- GEMM: xws[t] = dis_t * (x @ W[t]), fp16 single-pass ----------------
// smem: A[0,34816) B[34816,69632) dis[69632,+512). B region reused as fp16 out stage.
#define SM_B   34816u
#define SM_DIS 69632u
#define SMEM_BYTES 70144u

__global__ void __launch_bounds__(256, 2) k_gemm(const float* __restrict__ x) {
    extern __shared__ char sm[];
    uint32_t sb = smem_u32(sm);
    const int tid = threadIdx.x, lane = tid & 31, warp = tid >> 5;
    const int row0 = blockIdx.x * 128;
    const int wm = warp & 3, wn = warp >> 2;
    const int qr = lane >> 2, qc = lane & 3;

    // ---- A load: f32 -> fp16, once; reused for all 3 relations ----
    for (int i = tid; i < 4096; i += 256) {
        int r = i >> 5, c4 = i & 31;
        int gr = row0 + r;
        float4 v = make_float4(0.f, 0.f, 0.f, 0.f);
        if (gr < NN) v = *(const float4*)&x[(size_t)gr * D + c4 * 4];
        __half2 h0 = __float22half2_rn(make_float2(v.x, v.y));
        __half2 h1 = __float22half2_rn(make_float2(v.z, v.w));
        *(uint2*)(sm + (uint32_t)r * 272 + c4 * 8) =
            make_uint2(*(uint32_t*)&h0, *(uint32_t*)&h1);
    }

    const uint32_t aoff = sb + (uint32_t)(wm * 32 + (lane & 15)) * 272 + (lane >> 4) * 16;
    const uint32_t boff = sb + SM_B +
        (uint32_t)(wn * 64 + ((lane >> 3) & 1) * 8 + (lane & 7)) * 272 + (lane >> 4) * 16;

    for (int t = 0; t < TT; t++) {
        __syncthreads();   // A ready (t=0) / prev stage copy-out done
        const uint4* bsrc = g_wb + (size_t)t * (TILE_BYTES / 16);
        for (int i = tid; i < TILE_BYTES / 16; i += 256)
            ((uint4*)(sm + SM_B))[i] = bsrc[i];
        if (tid < 128) {
            int gr = row0 + tid;
            ((float*)(sm + SM_DIS))[tid] = (gr < NN) ? g_dis[t * NN + gr] : 0.f;
        }
        __syncthreads();

        float acc[2][8][4];
#pragma unroll
        for (int mt = 0; mt < 2; mt++)
#pragma unroll
            for (int nt = 0; nt < 8; nt++)
#pragma unroll
                for (int j = 0; j < 4; j++) acc[mt][nt][j] = 0.f;

#pragma unroll
        for (int ks = 0; ks < 8; ks++) {
            uint32_t ah[2][4];
#pragma unroll
            for (int mt = 0; mt < 2; mt++) {
                uint32_t a = aoff + mt * 4352 + ks * 32;
                LDSM4(ah[mt][0], ah[mt][1], ah[mt][2], ah[mt][3], a);
            }
#pragma unroll
            for (int j = 0; j < 4; j++) {
                uint32_t ba = boff + j * 4352 + ks * 32;
                uint32_t bh[4];
                LDSM4(bh[0], bh[1], bh[2], bh[3], ba);
#pragma unroll
                for (int mt = 0; mt < 2; mt++) {
                    MMA_F16(acc[mt][2 * j],     ah[mt][0], ah[mt][1], ah[mt][2], ah[mt][3], bh[0], bh[2]);
                    MMA_F16(acc[mt][2 * j + 1], ah[mt][0], ah[mt][1], ah[mt][2], ah[mt][3], bh[1], bh[3]);
                }
            }
        }

        // ---- epilogue: dis-scale, fp16 stage in B region, coalesced copy out ----
        __syncthreads();
#pragma unroll
        for (int mt = 0; mt < 2; mt++) {
            int r0 = wm * 32 + mt * 16 + qr;
            float s0 = ((float*)(sm + SM_DIS))[r0];
            float s1 = ((float*)(sm + SM_DIS))[r0 + 8];
#pragma unroll
            for (int nt = 0; nt < 8; nt++) {
                int col = wn * 64 + nt * 8 + qc * 2;
                *(__half2*)(sm + SM_B + (uint32_t)r0 * 272 + col * 2) =
                    __float22half2_rn(make_float2(acc[mt][nt][0] * s0, acc[mt][nt][1] * s0));
                *(__half2*)(sm + SM_B + (uint32_t)(r0 + 8) * 272 + col * 2) =
                    __float22half2_rn(make_float2(acc[mt][nt][2] * s1, acc[mt][nt][3] * s1));
            }
        }
        __syncthreads();
        for (int i = tid; i < 2048; i += 256) {
            int r = i >> 4, j = i & 15;
            int gr = row0 + r;
            if (gr < NN)
                *(uint4*)(g_xws + ((size_t)t * NN + gr) * D + j * 8) =
                    *(uint4*)(sm + SM_B + (uint32_t)r * 272 + j * 16);
        }
    }
}

// ---------------- gather: two nodes/warp, 4 entries per iteration, branch-free ----------------
__global__ void k_gather(const float* __restrict__ b, float* __restrict__ out) {
    int gw   = (blockIdx.x * blockDim.x + threadIdx.x) >> 5;   // warp id
    int lane = threadIdx.x & 31;
    const int half = lane >> 4;                                // 0 or 1
    const int l    = lane & 15;
    int w = gw * 2 + half;                                     // node id (per half-warp)
    if (w >= NN) return;
    const uint32_t lb = (uint32_t)l * 16;                      // byte offset within 256B row
    const char* xb = (const char*)g_xws;

    // bias sum as accumulator init: lane covers 8 fp32 cols [l*8, l*8+8)
    float acc[8];
    {
        float4 p0 = *(const float4*)&b[0 * D + l * 8];
        float4 p1 = *(const float4*)&b[0 * D + l * 8 + 4];
        float4 q0 = *(const float4*)&b[1 * D + l * 8];
        float4 q1 = *(const float4*)&b[1 * D + l * 8 + 4];
        float4 r0 = *(const float4*)&b[2 * D + l * 8];
        float4 r1 = *(const float4*)&b[2 * D + l * 8 + 4];
        acc[0] = p0.x + q0.x + r0.x; acc[1] = p0.y + q0.y + r0.y;
        acc[2] = p0.z + q0.z + r0.z; acc[3] = p0.w + q0.w + r0.w;
        acc[4] = p1.x + q1.x + r1.x; acc[5] = p1.y + q1.y + r1.y;
        acc[6] = p1.z + q1.z + r1.z; acc[7] = p1.w + q1.w + r1.w;
    }

#pragma unroll
    for (int t = 0; t < TT; t++) {
        int4 m = __ldg(&g_meta[t * NN + w]);   // {csr_base, cnt, dis_bits, cnt_pad4}
        const int4* cp = (const int4*)(g_csr + m.x);
        int n4 = m.w >> 2;                     // padded iterations
        float tmp[8];
#pragma unroll
        for (int j = 0; j < 8; j++) tmp[j] = 0.f;
#pragma unroll 2
        for (int i = 0; i < n4; i++) {
            int4 e = __ldg(cp + i);            // 4 entries, broadcast
            uint4 v0 = __ldg((const uint4*)(xb + (uint32_t)e.x + lb));
            uint4 v1 = __ldg((const uint4*)(xb + (uint32_t)e.y + lb));
            uint4 v2 = __ldg((const uint4*)(xb + (uint32_t)e.z + lb));
            uint4 v3 = __ldg((const uint4*)(xb + (uint32_t)e.w + lb));
#pragma unroll
            for (int q = 0; q < 4; q++) {
                uint4 v = (q == 0) ? v0 : (q == 1) ? v1 : (q == 2) ? v2 : v3;
                __half2* h2 = (__half2*)&v;
                float2 f0 = __half22float2(h2[0]);
                float2 f1 = __half22float2(h2[1]);
                float2 f2 = __half22float2(h2[2]);
                float2 f3 = __half22float2(h2[3]);
                tmp[0] += f0.x; tmp[1] += f0.y; tmp[2] += f1.x; tmp[3] += f1.y;
                tmp[4] += f2.x; tmp[5] += f2.y; tmp[6] += f3.x; tmp[7] += f3.y;
            }
        }
        float dn = __int_as_float(m.z);
#pragma unroll
        for (int j = 0; j < 8; j++) acc[j] += dn * tmp[j];
    }
    float* o = out + (size_t)w * D + l * 8;
    __stcs((float4*)o,       make_float4(acc[0], acc[1], acc[2], acc[3]));
    __stcs((float4*)(o + 4), make_float4(acc[4], acc[5], acc[6], acc[7]));
}

// ---------------------------------------------------------------------------
extern "C" void kernel_launch(void* const* d_in, const int* in_sizes, int n_in,
                              void* d_out, int out_size) {
    const float* x     = (const float*)d_in[0];   // [N, 128] f32
    const int*   edges = (const int*)d_in[1];     // [3, 2, E] i32
    const float* W     = (const float*)d_in[2];   // [3, 128, 128] f32
    const float* b     = (const float*)d_in[3];   // [3, 128] f32
    float* out = (float*)d_out;                   // [N, 128] f32

    cudaFuncSetAttribute(k_gemm, cudaFuncAttributeMaxDynamicSharedMemorySize, SMEM_BYTES);

    k_init<<<(TND + 255) / 256, 256>>>(W);
    k_fill<<<(TT * (EE / 4) + 255) / 256, 256>>>(edges);
    k_meta<<<(TND + 255) / 256, 256>>>();

    k_gemm<<<NCTA, 256, SMEM_BYTES>>>(x);

    // two nodes per warp -> NN/2 warps
    k_gather<<<((NN + 1) / 2 + 7) / 8, 256>>>(b, out);
}

// round 12
// speedup vs baseline: 1.0639x; 1.0639x over previous
#include <cuda_runtime.h>
#include <cuda_fp16.h>
#include <cstdint>

#define NN 100000
#define EE 800000
#define TT 3
#define D  128
#define TND (TT * NN)
#define NCTA 782           // ceil(NN/128)
#define TILE_BYTES 34816   // 128 * 272
#define BKT 48             // CSR bucket entries per (type,node); P(deg>48) ~ 3e-15
#define ZOFF (TND << 8)    // byte offset of the shared zero row

// ---------------- device scratch (no allocs allowed) ----------------
__device__ __half g_xws[((size_t)TND + 1) * D];     // 76.8 MB fp16 dis-scaled xw + zero row
__device__ uint4  g_wb[TT * (TILE_BYTES / 16)];     // W fp16 pre-baked smem images
__device__ int    g_cur[TND];                       // bucket fill cursor (starts at 1: self)
__device__ float  g_dis[TND];
__device__ int4   g_meta[TND];                      // {csr_base, cnt, dis_bits, cnt_pad4}
__device__ int    g_csr[(size_t)TND * BKT];         // absolute byte offsets ((t*NN+src)*256)

// ---------------- helpers ----------------
__device__ __forceinline__ uint32_t smem_u32(const void* p) {
    uint32_t a;
    asm("{ .reg .u64 t; cvta.to.shared.u64 t, %1; cvt.u32.u64 %0, t; }" : "=r"(a) : "l"(p));
    return a;
}

#define LDSM4(r0, r1, r2, r3, addr)                                              \
    asm volatile("ldmatrix.sync.aligned.m8n8.x4.shared.b16 {%0,%1,%2,%3}, [%4];" \
                 : "=r"(r0), "=r"(r1), "=r"(r2), "=r"(r3) : "r"(addr))

#define MMA_F16(d, a0, a1, a2, a3, b0, b1)                                    \
    asm volatile("mma.sync.aligned.m16n8k16.row.col.f32.f16.f16.f32 "         \
                 "{%0,%1,%2,%3}, {%4,%5,%6,%7}, {%8,%9}, {%0,%1,%2,%3};"      \
                 : "+f"(d[0]), "+f"(d[1]), "+f"(d[2]), "+f"(d[3])             \
                 : "r"(a0), "r"(a1), "r"(a2), "r"(a3), "r"(b0), "r"(b1))

// ---------------- init: cur=1, self entry, zero row, W fp16 prebake ----------------
__global__ void k_init(const float* __restrict__ W) {
    int i = blockIdx.x * blockDim.x + threadIdx.x;
    if (i < TND) {
        g_cur[i] = 1;                                // slot 0 = self loop
        g_csr[(size_t)i * BKT] = i << 8;             // self entry, absolute byte offset
    }
    if (i < 32)                                      // zero row (256B)
        ((uint2*)(g_xws + (size_t)TND * D))[i] = make_uint2(0u, 0u);
    if (i < TT * 128 * 32) {                         // W: one float4 per thread
        int t = i / (128 * 32);
        int k = (i >> 5) & 127;
        int c4 = i & 31;
        float4 v = *(const float4*)&W[(size_t)t * D * D + k * D + c4 * 4];
        float vv[4] = {v.x, v.y, v.z, v.w};
        unsigned char* img = (unsigned char*)g_wb + (size_t)t * TILE_BYTES;
#pragma unroll
        for (int j = 0; j < 4; j++) {
            int n = c4 * 4 + j;                      // output col -> B row
            *(__half*)(img + (size_t)n * 272 + k * 2) = __float2half_rn(vv[j]);
        }
    }
}

// ---------------- bucket fill: 4 edges per thread (EE % 4 == 0) ----------------
__global__ void k_fill(const int* __restrict__ edges) {
    int i = blockIdx.x * blockDim.x + threadIdx.x;
    if (i >= TT * (EE / 4)) return;
    int t = i / (EE / 4), e4 = i - t * (EE / 4);
    const int* et = edges + (size_t)t * 2 * EE;
    int4 s = __ldg((const int4*)et + e4);
    int4 d = __ldg((const int4*)(et + EE) + e4);
    int* cur = g_cur + t * NN;
    int tb = t * NN;
    int p;
    p = atomicAdd(&cur[d.x], 1); if (p < BKT) g_csr[(size_t)(tb + d.x) * BKT + p] = (tb + s.x) << 8;
    p = atomicAdd(&cur[d.y], 1); if (p < BKT) g_csr[(size_t)(tb + d.y) * BKT + p] = (tb + s.y) << 8;
    p = atomicAdd(&cur[d.z], 1); if (p < BKT) g_csr[(size_t)(tb + d.z) * BKT + p] = (tb + s.z) << 8;
    p = atomicAdd(&cur[d.w], 1); if (p < BKT) g_csr[(size_t)(tb + d.w) * BKT + p] = (tb + s.w) << 8;
}

// ---------------- meta: cnt + dis from cursors; pad buckets to mult of 4 ----------------
__global__ void k_meta() {
    int i = blockIdx.x * blockDim.x + threadIdx.x;
    if (i >= TND) return;
    int c = g_cur[i];
    c = (c < BKT) ? c : BKT;
    int c4 = (c + 3) & ~3;                           // padded count
    for (int s = c; s < c4; s++)                     // pad with zero-row entries
        g_csr[(size_t)i * BKT + s] = ZOFF;
    float dn = rsqrtf((float)c);                     // deg incl. self == entry count
    g_dis[i] = dn;
    g_meta[i] = make_int4(i * BKT, c, __float_as_int(dn), c4);
}

// ---------------- GEMM: xws[t] = dis_t * (x @ W[t]), fp16 single-pass ----------------
// smem: A[0,34816) B[34816,69632) dis[69632,+512). B region reused as fp16 out stage.
#define SM_B   34816u
#define SM_DIS 69632u
#define SMEM_BYTES 70144u

__global__ void __launch_bounds__(256, 2) k_gemm(const float* __restrict__ x) {
    extern __shared__ char sm[];
    uint32_t sb = smem_u32(sm);
    const int tid = threadIdx.x, lane = tid & 31, warp = tid >> 5;
    const int row0 = blockIdx.x * 128;
    const int wm = warp & 3, wn = warp >> 2;
    const int qr = lane >> 2, qc = lane & 3;

    // ---- A load: f32 -> fp16, once; reused for all 3 relations ----
    for (int i = tid; i < 4096; i += 256) {
        int r = i >> 5, c4 = i & 31;
        int gr = row0 + r;
        float4 v = make_float4(0.f, 0.f, 0.f, 0.f);
        if (gr < NN) v = *(const float4*)&x[(size_t)gr * D + c4 * 4];
        __half2 h0 = __float22half2_rn(make_float2(v.x, v.y));
        __half2 h1 = __float22half2_rn(make_float2(v.z, v.w));
        *(uint2*)(sm + (uint32_t)r * 272 + c4 * 8) =
            make_uint2(*(uint32_t*)&h0, *(uint32_t*)&h1);
    }

    const uint32_t aoff = sb + (uint32_t)(wm * 32 + (lane & 15)) * 272 + (lane >> 4) * 16;
    const uint32_t boff = sb + SM_B +
        (uint32_t)(wn * 64 + ((lane >> 3) & 1) * 8 + (lane & 7)) * 272 + (lane >> 4) * 16;

    for (int t = 0; t < TT; t++) {
        __syncthreads();   // A ready (t=0) / prev stage copy-out done
        const uint4* bsrc = g_wb + (size_t)t * (TILE_BYTES / 16);
        for (int i = tid; i < TILE_BYTES / 16; i += 256)
            ((uint4*)(sm + SM_B))[i] = bsrc[i];
        if (tid < 128) {
            int gr = row0 + tid;
            ((float*)(sm + SM_DIS))[tid] = (gr < NN) ? g_dis[t * NN + gr] : 0.f;
        }
        __syncthreads();

        float acc[2][8][4];
#pragma unroll
        for (int mt = 0; mt < 2; mt++)
#pragma unroll
            for (int nt = 0; nt < 8; nt++)
#pragma unroll
                for (int j = 0; j < 4; j++) acc[mt][nt][j] = 0.f;

#pragma unroll
        for (int ks = 0; ks < 8; ks++) {
            uint32_t ah[2][4];
#pragma unroll
            for (int mt = 0; mt < 2; mt++) {
                uint32_t a = aoff + mt * 4352 + ks * 32;
                LDSM4(ah[mt][0], ah[mt][1], ah[mt][2], ah[mt][3], a);
            }
#pragma unroll
            for (int j = 0; j < 4; j++) {
                uint32_t ba = boff + j * 4352 + ks * 32;
                uint32_t bh[4];
                LDSM4(bh[0], bh[1], bh[2], bh[3], ba);
#pragma unroll
                for (int mt = 0; mt < 2; mt++) {
                    MMA_F16(acc[mt][2 * j],     ah[mt][0], ah[mt][1], ah[mt][2], ah[mt][3], bh[0], bh[2]);
                    MMA_F16(acc[mt][2 * j + 1], ah[mt][0], ah[mt][1], ah[mt][2], ah[mt][3], bh[1], bh[3]);
                }
            }
        }

        // ---- epilogue: dis-scale, fp16 stage in B region, coalesced copy out ----
        __syncthreads();
#pragma unroll
        for (int mt = 0; mt < 2; mt++) {
            int r0 = wm * 32 + mt * 16 + qr;
            float s0 = ((float*)(sm + SM_DIS))[r0];
            float s1 = ((float*)(sm + SM_DIS))[r0 + 8];
#pragma unroll
            for (int nt = 0; nt < 8; nt++) {
                int col = wn * 64 + nt * 8 + qc * 2;
                *(__half2*)(sm + SM_B + (uint32_t)r0 * 272 + col * 2) =
                    __float22half2_rn(make_float2(acc[mt][nt][0] * s0, acc[mt][nt][1] * s0));
                *(__half2*)(sm + SM_B + (uint32_t)(r0 + 8) * 272 + col * 2) =
                    __float22half2_rn(make_float2(acc[mt][nt][2] * s1, acc[mt][nt][3] * s1));
            }
        }
        __syncthreads();
        for (int i = tid; i < 2048; i += 256) {
            int r = i >> 4, j = i & 15;
            int gr = row0 + r;
            if (gr < NN)
                *(uint4*)(g_xws + ((size_t)t * NN + gr) * D + j * 8) =
                    *(uint4*)(sm + SM_B + (uint32_t)r * 272 + j * 16);
        }
    }
}

// ---------------- gather: column-half pass; 2 nodes/warp, 8B lanes, 4-entry iters ---------
// Pass p touches only bytes [p*128, p*128+128) of each 256B row -> per-pass hot set
// = 38.4MB (all 3 types) -> L2-resident. out columns disjoint across passes.
__global__ void k_gather(const float* __restrict__ b, float* __restrict__ out, int pass) {
    int gw   = (blockIdx.x * blockDim.x + threadIdx.x) >> 5;   // warp id
    int lane = threadIdx.x & 31;
    const int half = lane >> 4;                                // 0 or 1
    const int l    = lane & 15;
    int w = gw * 2 + half;                                     // node id (per half-warp)
    if (w >= NN) return;
    const uint32_t lb = (uint32_t)pass * 128 + (uint32_t)l * 8;  // byte offset in row
    const int col0 = pass * 64 + l * 4;                          // 4 fp32 out cols
    const char* xb = (const char*)g_xws;

    // bias sum as accumulator init
    float acc[4];
    {
        float4 b0 = *(const float4*)&b[0 * D + col0];
        float4 b1 = *(const float4*)&b[1 * D + col0];
        float4 b2 = *(const float4*)&b[2 * D + col0];
        acc[0] = b0.x + b1.x + b2.x; acc[1] = b0.y + b1.y + b2.y;
        acc[2] = b0.z + b1.z + b2.z; acc[3] = b0.w + b1.w + b2.w;
    }

#pragma unroll
    for (int t = 0; t < TT; t++) {
        int4 m = __ldg(&g_meta[t * NN + w]);   // {csr_base, cnt, dis_bits, cnt_pad4}
        const int4* cp = (const int4*)(g_csr + m.x);
        int n4 = m.w >> 2;                     // padded iterations
        float tmp[4] = {0.f, 0.f, 0.f, 0.f};
#pragma unroll 2
        for (int i = 0; i < n4; i++) {
            int4 e = __ldg(cp + i);            // 4 entries, broadcast per half-warp
            uint2 v0 = __ldg((const uint2*)(xb + (uint32_t)e.x + lb));
            uint2 v1 = __ldg((const uint2*)(xb + (uint32_t)e.y + lb));
            uint2 v2 = __ldg((const uint2*)(xb + (uint32_t)e.z + lb));
            uint2 v3 = __ldg((const uint2*)(xb + (uint32_t)e.w + lb));
#pragma unroll
            for (int q = 0; q < 4; q++) {
                uint2 v = (q == 0) ? v0 : (q == 1) ? v1 : (q == 2) ? v2 : v3;
                __half2* h2 = (__half2*)&v;
                float2 f0 = __half22float2(h2[0]);
                float2 f1 = __half22float2(h2[1]);
                tmp[0] += f0.x; tmp[1] += f0.y; tmp[2] += f1.x; tmp[3] += f1.y;
            }
        }
        float dn = __int_as_float(m.z);
#pragma unroll
        for (int j = 0; j < 4; j++) acc[j] += dn * tmp[j];
    }
    __stcs((float4*)&out[(size_t)w * D + col0],
           make_float4(acc[0], acc[1], acc[2], acc[3]));
}

// ---------------------------------------------------------------------------
extern "C" void kernel_launch(void* const* d_in, const int* in_sizes, int n_in,
                              void* d_out, int out_size) {
    const float* x     = (const float*)d_in[0];   // [N, 128] f32
    const int*   edges = (const int*)d_in[1];     // [3, 2, E] i32
    const float* W     = (const float*)d_in[2];   // [3, 128, 128] f32
    const float* b     = (const float*)d_in[3];   // [3, 128] f32
    float* out = (float*)d_out;                   // [N, 128] f32

    cudaFuncSetAttribute(k_gemm, cudaFuncAttributeMaxDynamicSharedMemorySize, SMEM_BYTES);

    k_init<<<(TND + 255) / 256, 256>>>(W);
    k_fill<<<(TT * (EE / 4) + 255) / 256, 256>>>(edges);
    k_meta<<<(TND + 255) / 256, 256>>>();

    k_gemm<<<NCTA, 256, SMEM_BYTES>>>(x);

    // two sequential column-half passes -> per-pass xws hot set 38.4MB (L2-resident)
    const int GBLK = ((NN + 1) / 2 + 7) / 8;
    k_gather<<<GBLK, 256>>>(b, out, 0);
    k_gather<<<GBLK, 256>>>(b, out, 1);
}